// round 6
// baseline (speedup 1.0000x reference)
#include <cuda_runtime.h>

// SparseDownSample: 2x2 max-pool keyed on depth (first-max tie-break),
// gather winning position from depth (1ch) and geo (16ch).
// depth: [B,1,H,W] f32, geo: [B,C,H,W] f32
// out  : depth_fold [B,1,H/2,W/2] followed by geo_fold [B,C,H/2,W/2]
//
// This version: 4 output pixels per thread (2 input rows x 8 cols = 2 float4
// per row per channel), STG.128 stores, CB-channel staged load batches.

constexpr int B  = 8;
constexpr int C  = 16;
constexpr int H  = 352;
constexpr int W  = 1216;
constexpr int H2 = H / 2;    // 176
constexpr int W2 = W / 2;    // 608
constexpr int WQ = W2 / 4;   // 152 output float4s per row (8 input cols each)
constexpr int DEPTH_OUT_ELEMS = B * H2 * W2;  // 856064
constexpr int CB = 4;        // channels per load batch (16 float4 = 64 regs live)

// argmax over 2x2 window, first-max wins. order: 0=(r0,c0) 1=(r0,c1)
// 2=(r1,c0) 3=(r1,c1) -- matches unfold kh,kw ordering.
__device__ __forceinline__ int argmax4(float a, float b, float c, float d, float& v)
{
    int i = 0; v = a;
    if (b > v) { v = b; i = 1; }
    if (c > v) { v = c; i = 2; }
    if (d > v) { v = d; i = 3; }
    return i;
}

__device__ __forceinline__ float sel4(int i, float a, float b, float c, float d)
{
    return (i == 0) ? a : (i == 1) ? b : (i == 2) ? c : d;
}

__global__ __launch_bounds__(256)
void sds_kernel(const float* __restrict__ depth,
                const float* __restrict__ geo,
                float* __restrict__ out)
{
    const int t = blockIdx.x * blockDim.x + threadIdx.x;
    const int total = B * H2 * WQ;   // 214016
    if (t >= total) return;

    const int xq   = t % WQ;         // which output-float4 within the row
    const int rest = t / WQ;
    const int y    = rest % H2;
    const int b    = rest / H2;

    // ---- depth: two rows, two float4 each (covers 4 output pixels) ----
    const float* drow = depth + (size_t)(b * H + 2 * y) * W;
    const float4 d00 = __ldcs(reinterpret_cast<const float4*>(drow)     + 2 * xq);
    const float4 d01 = __ldcs(reinterpret_cast<const float4*>(drow)     + 2 * xq + 1);
    const float4 d10 = __ldcs(reinterpret_cast<const float4*>(drow + W) + 2 * xq);
    const float4 d11 = __ldcs(reinterpret_cast<const float4*>(drow + W) + 2 * xq + 1);

    float v0, v1, v2, v3;
    const int i0 = argmax4(d00.x, d00.y, d10.x, d10.y, v0);
    const int i1 = argmax4(d00.z, d00.w, d10.z, d10.w, v1);
    const int i2 = argmax4(d01.x, d01.y, d11.x, d11.y, v2);
    const int i3 = argmax4(d01.z, d01.w, d11.z, d11.w, v3);

    // depth_fold store (float4, 16B aligned: xq*4 elems)
    const size_t dpix = (size_t)(b * H2 + y) * W2 + (size_t)xq * 4;
    __stcs(reinterpret_cast<float4*>(out) + dpix / 4, make_float4(v0, v1, v2, v3));

    // ---- geo: 16 channels in batches of CB; stage loads, then select ----
    float* gout = out + DEPTH_OUT_ELEMS;
    const float* grow = geo + ((size_t)b * C * H + 2 * y) * W;   // channel 0, row 2y
    const size_t obase = ((size_t)(b * C) * H2 + y) * W2 + (size_t)xq * 4;

    #pragma unroll
    for (int cb = 0; cb < C; cb += CB) {
        float4 g00[CB], g01[CB], g10[CB], g11[CB];
        // phase 1: issue all loads back-to-back (front-batched 4*CB LDG.128)
        #pragma unroll
        for (int j = 0; j < CB; ++j) {
            const float* r0 = grow + (size_t)(cb + j) * (H * W);
            g00[j] = __ldcs(reinterpret_cast<const float4*>(r0)     + 2 * xq);
            g01[j] = __ldcs(reinterpret_cast<const float4*>(r0)     + 2 * xq + 1);
            g10[j] = __ldcs(reinterpret_cast<const float4*>(r0 + W) + 2 * xq);
            g11[j] = __ldcs(reinterpret_cast<const float4*>(r0 + W) + 2 * xq + 1);
        }
        // phase 2: select + STG.128 store
        #pragma unroll
        for (int j = 0; j < CB; ++j) {
            float4 s;
            s.x = sel4(i0, g00[j].x, g00[j].y, g10[j].x, g10[j].y);
            s.y = sel4(i1, g00[j].z, g00[j].w, g10[j].z, g10[j].w);
            s.z = sel4(i2, g01[j].x, g01[j].y, g11[j].x, g11[j].y);
            s.w = sel4(i3, g01[j].z, g01[j].w, g11[j].z, g11[j].w);
            const size_t o = obase + (size_t)(cb + j) * (H2 * W2);
            __stcs(reinterpret_cast<float4*>(gout) + o / 4, s);
        }
    }
}

extern "C" void kernel_launch(void* const* d_in, const int* in_sizes, int n_in,
                              void* d_out, int out_size)
{
    const float* depth = (const float*)d_in[0];
    const float* geo   = (const float*)d_in[1];
    float* out = (float*)d_out;

    const int total   = B * H2 * WQ;          // 214016 threads
    const int threads = 256;
    const int blocks  = (total + threads - 1) / threads;
    sds_kernel<<<blocks, threads>>>(depth, geo, out);
}

// round 7
// speedup vs baseline: 1.0336x; 1.0336x over previous
#include <cuda_runtime.h>

// SparseDownSample: 2x2 max-pool keyed on depth (first-max tie-break),
// gather winning position from depth (1ch) and geo (16ch).
// depth: [B,1,H,W] f32, geo: [B,C,H,W] f32
// out  : depth_fold [B,1,H/2,W/2] followed by geo_fold [B,C,H/2,W/2]
//
// R7: 2 output px/thread (lane-dense float4 loads), FULL staging: depth(2) +
// all 16 channels (32) = 34 front-batched LDG.128, then one select/store phase.

constexpr int B  = 8;
constexpr int C  = 16;
constexpr int H  = 352;
constexpr int W  = 1216;
constexpr int H2 = H / 2;    // 176
constexpr int W2 = W / 2;    // 608
constexpr int WP = W2 / 2;   // 304 output-pixel PAIRS per row (one float4 of input per row)
constexpr int DEPTH_OUT_ELEMS = B * H2 * W2;  // 856064

__global__ __launch_bounds__(128)
void sds_kernel(const float* __restrict__ depth,
                const float* __restrict__ geo,
                float* __restrict__ out)
{
    const int t = blockIdx.x * blockDim.x + threadIdx.x;
    const int total = B * H2 * WP;   // 428032
    if (t >= total) return;

    const int xp   = t % WP;         // which float4 within the row
    const int rest = t / WP;
    const int y    = rest % H2;
    const int b    = rest / H2;

    // ================= phase 1: issue ALL loads back-to-back =================
    const float* drow = depth + (size_t)(b * H + 2 * y) * W;
    const float4 d0 = __ldcs(reinterpret_cast<const float4*>(drow)     + xp);
    const float4 d1 = __ldcs(reinterpret_cast<const float4*>(drow + W) + xp);

    const float* grow = geo + ((size_t)b * C * H + 2 * y) * W;   // channel 0, row 2y
    float4 g0[C], g1[C];
    #pragma unroll
    for (int c = 0; c < C; ++c) {
        const float* r0 = grow + (size_t)c * (H * W);
        g0[c] = __ldcs(reinterpret_cast<const float4*>(r0)     + xp);
        g1[c] = __ldcs(reinterpret_cast<const float4*>(r0 + W) + xp);
    }

    // ================= phase 2: argmax, select, store ========================
    // argmax, first-max wins (strict > keeps lowest index), order:
    // 0=(r0,c0) 1=(r0,c1) 2=(r1,c0) 3=(r1,c1)  -- matches unfold kh,kw ordering
    int   i0 = 0; float v0 = d0.x;
    if (d0.y > v0) { v0 = d0.y; i0 = 1; }
    if (d1.x > v0) { v0 = d1.x; i0 = 2; }
    if (d1.y > v0) { v0 = d1.y; i0 = 3; }

    int   i1 = 0; float v1 = d0.z;
    if (d0.w > v1) { v1 = d0.w; i1 = 1; }
    if (d1.z > v1) { v1 = d1.z; i1 = 2; }
    if (d1.w > v1) { v1 = d1.w; i1 = 3; }

    const size_t dpix = (size_t)(b * H2 + y) * W2 + (size_t)xp * 2;
    __stcs(reinterpret_cast<float2*>(out) + dpix / 2, make_float2(v0, v1));

    float* gout = out + DEPTH_OUT_ELEMS;
    const size_t obase = ((size_t)(b * C) * H2 + y) * W2 + (size_t)xp * 2;

    #pragma unroll
    for (int c = 0; c < C; ++c) {
        const float s0 = (i0 == 0) ? g0[c].x : (i0 == 1) ? g0[c].y
                       : (i0 == 2) ? g1[c].x : g1[c].y;
        const float s1 = (i1 == 0) ? g0[c].z : (i1 == 1) ? g0[c].w
                       : (i1 == 2) ? g1[c].z : g1[c].w;
        const size_t o = obase + (size_t)c * (H2 * W2);
        __stcs(reinterpret_cast<float2*>(gout) + o / 2, make_float2(s0, s1));
    }
}

extern "C" void kernel_launch(void* const* d_in, const int* in_sizes, int n_in,
                              void* d_out, int out_size)
{
    const float* depth = (const float*)d_in[0];
    const float* geo   = (const float*)d_in[1];
    float* out = (float*)d_out;

    const int total   = B * H2 * WP;          // 428032 threads
    const int threads = 128;
    const int blocks  = (total + threads - 1) / threads;
    sds_kernel<<<blocks, threads>>>(depth, geo, out);
}